// round 9
// baseline (speedup 1.0000x reference)
#include <cuda_runtime.h>

#define S 26
#define D 7
#define DA 11
#define V 29
#define NT 384
#define TRI (S*(S+1)/2)   // 351

__global__ __launch_bounds__(NT, 1)
void bes_transformer_kernel(
    const int*   __restrict__ x,
    const float* __restrict__ emb_table,
    const float* __restrict__ pos,
    const float* __restrict__ wk0, const float* __restrict__ bk0,
    const float* __restrict__ wq0, const float* __restrict__ bq0,
    const float* __restrict__ wv0, const float* __restrict__ bv0,
    const float* __restrict__ wf0, const float* __restrict__ bf0,
    const float* __restrict__ wk1, const float* __restrict__ bk1,
    const float* __restrict__ wq1, const float* __restrict__ bq1,
    const float* __restrict__ wv1, const float* __restrict__ bv1,
    const float* __restrict__ wf1, const float* __restrict__ bf1,
    const float* __restrict__ wout, const float* __restrict__ bout,
    float* __restrict__ out)
{
    __shared__ float h[S][D];
    __shared__ float k[S][DA], q[S][DA], v[S][DA];
    __shared__ float att[S][S];
    __shared__ float res[S][DA];
    __shared__ float inv_s[S];
    __shared__ float aug[3][DA][12];   // fused layer-1 QKV: [W·Wf0 | W·bf0+b]
    __shared__ float augo[V][12];      // fused logits:      [Wout·Wf1 | Wout·bf1+bout]

    const int t = threadIdx.x;

    // packed lower-triangle coords for score stages
    int tr = 0, tc = 0;
    if (t < TRI) {
        tr = (int)((sqrtf(8.f * (float)t + 1.f) - 1.f) * 0.5f);
        if (t < tr * (tr + 1) / 2) tr--;
        if (t >= (tr + 1) * (tr + 2) / 2) tr++;
        tc = t - tr * (tr + 1) / 2;
    }

    // ================= stage 0: embedding + fused-weight precompute ========
    if (t < S * D) {
        int s = t / D, d = t % D;
        h[s][d] = emb_table[x[s] * D + d] + pos[t];
    }
    // 744 precompute elems: 3 aug QKV1 (3*11*12=396) + augo (29*12=348)
    for (int i = t; i < 744; i += NT) {
        if (i < 396) {
            int m = i / 132, rem = i % 132, a = rem / 12, j = rem % 12;
            const float* W = (m == 0) ? wk1 : (m == 1) ? wq1 : wv1;
            const float* B = (m == 0) ? bk1 : (m == 1) ? bq1 : bv1;
            float acc;
            if (j < DA) {
                acc = 0.f;
                #pragma unroll
                for (int d = 0; d < D; d++) acc += W[a * D + d] * wf0[d * DA + j];
            } else {
                acc = B[a];
                #pragma unroll
                for (int d = 0; d < D; d++) acc += W[a * D + d] * bf0[d];
            }
            aug[m][a][j] = acc;
        } else {
            int o = i - 396, vr = o / 12, j = o % 12;
            float acc;
            if (j < DA) {
                acc = 0.f;
                #pragma unroll
                for (int d = 0; d < D; d++) acc += wout[vr * D + d] * wf1[d * DA + j];
            } else {
                acc = bout[vr];
                #pragma unroll
                for (int d = 0; d < D; d++) acc += wout[vr * D + d] * bf1[d];
            }
            augo[vr][j] = acc;
        }
    }
    __syncthreads();

    // ================= stage 1: QKV layer 0 (286 elems, single shot) =======
    if (t < S * DA) {
        int s = t / DA, a = t % DA;
        float sk = bk0[a], sq = bq0[a], sv = bv0[a];
        #pragma unroll
        for (int d = 0; d < D; d++) {
            float hv = h[s][d];
            sk += hv * wk0[a * D + d];
            sq += hv * wq0[a * D + d];
            sv += hv * wv0[a * D + d];
        }
        k[s][a] = sk; q[s][a] = sq; v[s][a] = sv;
    }
    __syncthreads();

    // ================= stage 2: scores 0 (packed triangle, single shot) ====
    if (t < TRI) {
        float sum = 0.f;
        #pragma unroll
        for (int a = 0; a < DA; a++) sum += q[tr][a] * k[tc][a];
        att[tr][tc] = __expf(sum);
    }
    __syncthreads();

    // ================= stage 3: AV0 + normalize (causal loop) ==============
    if (t < S * DA) {
        int s = t / DA, a = t % DA;
        float sum = 0.f, dot = 0.f;
        for (int c = 0; c <= s; c++) {
            float e = att[s][c];
            sum += e;
            dot += e * v[c][a];
        }
        res[s][a] = dot * __frcp_rn(sum);
    }
    __syncthreads();

    // ================= stage 4: fused QKV layer 1 from res0 ================
    if (t < S * DA) {
        int s = t / DA, a = t % DA;
        float sk = aug[0][a][11], sq = aug[1][a][11], sv = aug[2][a][11];
        #pragma unroll
        for (int j = 0; j < DA; j++) {
            float rv = res[s][j];
            sk += rv * aug[0][a][j];
            sq += rv * aug[1][a][j];
            sv += rv * aug[2][a][j];
        }
        k[s][a] = sk; q[s][a] = sq; v[s][a] = sv;
    }
    __syncthreads();

    // ================= stage 5: scores 1 ===================================
    if (t < TRI) {
        float sum = 0.f;
        #pragma unroll
        for (int a = 0; a < DA; a++) sum += q[tr][a] * k[tc][a];
        att[tr][tc] = __expf(sum);
    }
    __syncthreads();

    // ================= stage 6: AV1 + normalize ============================
    if (t < S * DA) {
        int s = t / DA, a = t % DA;
        float sum = 0.f, dot = 0.f;
        for (int c = 0; c <= s; c++) {
            float e = att[s][c];
            sum += e;
            dot += e * v[c][a];
        }
        float iv = __frcp_rn(sum);
        res[s][a] = dot * iv;
        if (a == 0) inv_s[s] = iv;
    }
    __syncthreads();

    // ================= stage 7: fused logits + att output ==================
    for (int i = t; i < S * V; i += NT) {
        int s = i / V, vv = i % V;
        float val = augo[vv][11];
        #pragma unroll
        for (int j = 0; j < DA; j++) val += res[s][j] * augo[vv][j];
        out[i] = val;
    }
    for (int i = t; i < S * S; i += NT) {
        int r = i / S, c = i % S;
        out[S * V + i] = (c <= r) ? att[r][c] * inv_s[r] : 0.f;
    }
}

extern "C" void kernel_launch(void* const* d_in, const int* in_sizes, int n_in,
                              void* d_out, int out_size)
{
    bes_transformer_kernel<<<1, NT>>>(
        (const int*)  d_in[0],   // x
        (const float*)d_in[1],   // emb_table
        (const float*)d_in[2],   // pos
        (const float*)d_in[3],  (const float*)d_in[4],   // w_k0, b_k0
        (const float*)d_in[5],  (const float*)d_in[6],   // w_q0, b_q0
        (const float*)d_in[7],  (const float*)d_in[8],   // w_v0, b_v0
        (const float*)d_in[9],  (const float*)d_in[10],  // w_f0, b_f0
        (const float*)d_in[11], (const float*)d_in[12],  // w_k1, b_k1
        (const float*)d_in[13], (const float*)d_in[14],  // w_q1, b_q1
        (const float*)d_in[15], (const float*)d_in[16],  // w_v1, b_v1
        (const float*)d_in[17], (const float*)d_in[18],  // w_f1, b_f1
        (const float*)d_in[19], (const float*)d_in[20],  // w_out, b_out
        (float*)d_out);
}

// round 10
// speedup vs baseline: 1.2077x; 1.2077x over previous
#include <cuda_runtime.h>

#define S 26
#define D 7
#define DA 11
#define V 29
#define NT 384
#define TRI (S*(S+1)/2)   // 351
#define LOG2E 1.4426950408889634f

__device__ __forceinline__ float ex2(float x) {
    float y; asm("ex2.approx.f32 %0, %1;" : "=f"(y) : "f"(x)); return y;
}
__device__ __forceinline__ float rcpa(float x) {
    float y; asm("rcp.approx.f32 %0, %1;" : "=f"(y) : "f"(x)); return y;
}

__global__ __launch_bounds__(NT, 1)
void bes_transformer_kernel(
    const int*   __restrict__ x,
    const float* __restrict__ emb_table,
    const float* __restrict__ pos,
    const float* __restrict__ wk0, const float* __restrict__ bk0,
    const float* __restrict__ wq0, const float* __restrict__ bq0,
    const float* __restrict__ wv0, const float* __restrict__ bv0,
    const float* __restrict__ wf0, const float* __restrict__ bf0,
    const float* __restrict__ wk1, const float* __restrict__ bk1,
    const float* __restrict__ wq1, const float* __restrict__ bq1,
    const float* __restrict__ wv1, const float* __restrict__ bv1,
    const float* __restrict__ wf1, const float* __restrict__ bf1,
    const float* __restrict__ wout, const float* __restrict__ bout,
    float* __restrict__ out)
{
    __shared__ float h[S][D];
    __shared__ float k[S][DA];
    __shared__ float q[S][DA];    // pre-scaled by log2(e)
    __shared__ float v[S][DA];
    __shared__ float att[S][S];   // lower triangle only; upper is garbage
    __shared__ float res[S][DA];
    __shared__ float inv_s[S];

    const int t = threadIdx.x;

    // packed lower-triangle coords (t < TRI)
    int tr = 0, tc = 0;
    if (t < TRI) {
        tr = (int)((sqrtf(8.f * (float)t + 1.f) - 1.f) * 0.5f);
        if (t < tr * (tr + 1) / 2) tr--;
        if (t >= (tr + 1) * (tr + 2) / 2) tr++;
        tc = t - tr * (tr + 1) / 2;
    }

    // ---- stage 0: embedding + positional ----
    if (t < S * D) {
        int s = t / D, d = t % D;
        h[s][d] = emb_table[x[s] * D + d] + pos[t];
    }
    __syncthreads();

    #pragma unroll 1
    for (int layer = 0; layer < 2; layer++) {
        const float* wk = layer ? wk1 : wk0;
        const float* bk = layer ? bk1 : bk0;
        const float* wq = layer ? wq1 : wq0;
        const float* bq = layer ? bq1 : bq0;
        const float* wv = layer ? wv1 : wv0;
        const float* bv = layer ? bv1 : bv0;
        const float* wf = layer ? wf1 : wf0;
        const float* bf = layer ? bf1 : bf0;

        // ---- QKV projections (286 elems, single shot); q scaled by log2e ----
        if (t < S * DA) {
            int s = t / DA, a = t % DA;
            float sk = bk[a], sq = bq[a], sv = bv[a];
            #pragma unroll
            for (int d = 0; d < D; d++) {
                float hv = h[s][d];
                sk += hv * wk[a * D + d];
                sq += hv * wq[a * D + d];
                sv += hv * wv[a * D + d];
            }
            k[s][a] = sk; q[s][a] = sq * LOG2E; v[s][a] = sv;
        }
        __syncthreads();

        // ---- scores: packed lower triangle, single shot, ex2 direct ----
        if (t < TRI) {
            float sum = 0.f;
            #pragma unroll
            for (int a = 0; a < DA; a++) sum += q[tr][a] * k[tc][a];
            att[tr][tc] = ex2(sum);
        }
        __syncthreads();

        // ---- AV + normalize (causal trip count, single shot) ----
        if (t < S * DA) {
            int s = t / DA, a = t % DA;
            float sum = 0.f, dot = 0.f;
            for (int c = 0; c <= s; c++) {
                float e = att[s][c];
                sum += e;
                dot += e * v[c][a];
            }
            float iv = rcpa(sum);
            res[s][a] = dot * iv;
            if (a == 0) inv_s[s] = iv;
        }
        __syncthreads();

        // ---- h = res @ wf^T + bf; layer-1 att rows to output in parallel ----
        if (t < S * D) {
            int s = t / D, d = t % D;
            float r = bf[d];
            #pragma unroll
            for (int a = 0; a < DA; a++) r += res[s][a] * wf[d * DA + a];
            h[s][d] = r;
        }
        if (layer == 1) {
            for (int i = t; i < S * S; i += NT) {
                int r = i / S, c = i % S;
                out[S * V + i] = (c <= r) ? att[r][c] * inv_s[r] : 0.f;
            }
        }
        __syncthreads();
    }

    // ---- logits: out = h @ wout^T + bout (754 elems, 2 shots) ----
    for (int i = t; i < S * V; i += NT) {
        int s = i / V, vv = i % V;
        float r = bout[vv];
        #pragma unroll
        for (int d = 0; d < D; d++) r += h[s][d] * wout[vv * D + d];
        out[i] = r;
    }
}

extern "C" void kernel_launch(void* const* d_in, const int* in_sizes, int n_in,
                              void* d_out, int out_size)
{
    bes_transformer_kernel<<<1, NT>>>(
        (const int*)  d_in[0],   // x
        (const float*)d_in[1],   // emb_table
        (const float*)d_in[2],   // pos
        (const float*)d_in[3],  (const float*)d_in[4],   // w_k0, b_k0
        (const float*)d_in[5],  (const float*)d_in[6],   // w_q0, b_q0
        (const float*)d_in[7],  (const float*)d_in[8],   // w_v0, b_v0
        (const float*)d_in[9],  (const float*)d_in[10],  // w_f0, b_f0
        (const float*)d_in[11], (const float*)d_in[12],  // w_k1, b_k1
        (const float*)d_in[13], (const float*)d_in[14],  // w_q1, b_q1
        (const float*)d_in[15], (const float*)d_in[16],  // w_v1, b_v1
        (const float*)d_in[17], (const float*)d_in[18],  // w_f1, b_f1
        (const float*)d_in[19], (const float*)d_in[20],  // w_out, b_out
        (float*)d_out);
}